// round 8
// baseline (speedup 1.0000x reference)
#include <cuda_runtime.h>
#include <cuda_bf16.h>
#include <cuda_fp16.h>
#include <cstdint>
#include <math.h>

#define N_NODES 50000
#define N_EDGES 500000
#define EN      (N_EDGES + N_NODES)   // 550000 incl. self loops
#define D_IN    128
#define D_HID   256
#define BM      128
#define BN      128
#define BK      64
#define N_CTAS  ((N_NODES + BM - 1) / BM)   // 391
#define M_PAD   (N_CTAS * BM)               // 50048

// ---------------- async-copy helpers (portable PTX, sm_80+) -----------------
__device__ __forceinline__ uint32_t smem_to_u32(const void* p) {
    uint32_t a;
    asm("{ .reg .u64 t; cvta.to.shared.u64 t, %1; cvt.u32.u64 %0, t; }" : "=r"(a) : "l"(p));
    return a;
}
__device__ __forceinline__ void cp_async16(uint32_t s, const void* g) {
    asm volatile("cp.async.cg.shared.global [%0], [%1], 16;" :: "r"(s), "l"(g));
}
__device__ __forceinline__ void cp_commit() {
    asm volatile("cp.async.commit_group;" ::: "memory");
}
template <int N>
__device__ __forceinline__ void cp_wait() {
    asm volatile("cp.async.wait_group %0;" :: "n"(N) : "memory");
}
__device__ __forceinline__ void ldsm_x4(uint32_t* r, uint32_t addr) {
    asm volatile("ldmatrix.sync.aligned.m8n8.x4.shared.b16 {%0,%1,%2,%3}, [%4];"
                 : "=r"(r[0]), "=r"(r[1]), "=r"(r[2]), "=r"(r[3]) : "r"(addr));
}
__device__ __forceinline__ void mma_bf16(float* c, const uint32_t* a, const uint32_t* b) {
    asm volatile(
        "mma.sync.aligned.m16n8k16.row.col.f32.bf16.bf16.f32 "
        "{%0,%1,%2,%3}, {%4,%5,%6,%7}, {%8,%9}, {%0,%1,%2,%3};"
        : "+f"(c[0]), "+f"(c[1]), "+f"(c[2]), "+f"(c[3])
        : "r"(a[0]), "r"(a[1]), "r"(a[2]), "r"(a[3]), "r"(b[0]), "r"(b[1]));
}

// ---------------- device scratch (static globals; no allocation) ------------
__device__ int   g_deg[N_NODES];          // zeroed each replay by k_scan
__device__ int   g_row_ptr[N_NODES + 1];
__device__ int   g_pos[N_NODES];
__device__ int   g_col[EN];
__device__ float g_enorm[EN];
__device__ float g_dinv[N_NODES];
__device__ __align__(16) __half g_x16[(size_t)N_NODES * D_IN];         // fp16 copy of x
__device__ __align__(16) __half g_h16[(size_t)N_NODES * D_HID];        // fp16 activations
__device__ __align__(16) __nv_bfloat16 g_ah[(size_t)M_PAD * D_HID];    // split-hi of agg
__device__ __align__(16) __nv_bfloat16 g_al[(size_t)M_PAD * D_HID];    // split-lo of agg
__device__ __align__(16) __nv_bfloat16 g_w1h[D_HID * D_IN];            // W^T [256,128]
__device__ __align__(16) __nv_bfloat16 g_w1l[D_HID * D_IN];
__device__ __align__(16) __nv_bfloat16 g_w2h[D_HID * D_HID];           // W^T [256,256]
__device__ __align__(16) __nv_bfloat16 g_w2l[D_HID * D_HID];
__device__ __align__(16) __nv_bfloat16 g_w3h[D_HID * D_HID];
__device__ __align__(16) __nv_bfloat16 g_w3l[D_HID * D_HID];

// ---------------- fused launch 1: degree count + W split + x->fp16 ----------
#define W1_ELEMS (D_IN * D_HID)
#define W23_ELEMS (D_HID * D_HID)
#define SPLIT_ELEMS (W1_ELEMS + 2 * W23_ELEMS)   // 163840
#define XCVT_THREADS ((N_NODES * D_IN) / 4)      // 1.6M (4 floats/thread)
#define L1_THREADS (N_EDGES + SPLIT_ELEMS + XCVT_THREADS)

__device__ __forceinline__ void split_one(const float* W, int K, int idx,
                                          __nv_bfloat16* oh, __nv_bfloat16* ol) {
    int k = idx / D_HID, n = idx % D_HID;
    float v = W[idx];
    __nv_bfloat16 h = __float2bfloat16(v);
    oh[(size_t)n * K + k] = h;
    ol[(size_t)n * K + k] = __float2bfloat16(v - __bfloat162float(h));
}

__global__ void k_count_split(const int* __restrict__ ei,
                              const float* __restrict__ W1,
                              const float* __restrict__ W2,
                              const float* __restrict__ W3,
                              const float* __restrict__ x) {
    int idx = blockIdx.x * blockDim.x + threadIdx.x;
    if (idx < N_EDGES) {
        atomicAdd(&g_deg[ei[N_EDGES + idx]], 1);
        return;
    }
    int j = idx - N_EDGES;
    if (j < W1_ELEMS) { split_one(W1, D_IN, j, g_w1h, g_w1l); return; }
    j -= W1_ELEMS;
    if (j < W23_ELEMS) { split_one(W2, D_HID, j, g_w2h, g_w2l); return; }
    j -= W23_ELEMS;
    if (j < W23_ELEMS) { split_one(W3, D_HID, j, g_w3h, g_w3l); return; }
    j -= W23_ELEMS;
    if (j < XCVT_THREADS) {
        float4 v = reinterpret_cast<const float4*>(x)[j];
        __half2* o = reinterpret_cast<__half2*>(g_x16) + (size_t)j * 2;
        o[0] = __floats2half2_rn(v.x, v.y);
        o[1] = __floats2half2_rn(v.z, v.w);
    }
}

// Single-block scan. Degree = g_deg[i] + 1 (self loop). Zeroes g_deg for the
// next replay (deterministic).
__global__ void k_scan() {
    __shared__ int s[1024];
    const int t = threadIdx.x;
    const int CH = (N_NODES + 1023) / 1024;
    int start = t * CH;
    int end = start + CH; if (end > N_NODES) end = N_NODES;
    if (start > N_NODES) start = N_NODES;
    int sum = 0;
#pragma unroll 4
    for (int i = start; i < end; i++) sum += g_deg[i] + 1;
    s[t] = sum;
    __syncthreads();
    for (int off = 1; off < 1024; off <<= 1) {
        int v = (t >= off) ? s[t - off] : 0;
        __syncthreads();
        s[t] += v;
        __syncthreads();
    }
    int prefix = (t == 0) ? 0 : s[t - 1];
    for (int i = start; i < end; i++) {
        int d = g_deg[i] + 1;
        g_deg[i] = 0;
        g_row_ptr[i] = prefix;
        g_pos[i] = prefix;
        g_dinv[i] = rsqrtf((float)d);
        prefix += d;
    }
    if (t == 0) g_row_ptr[N_NODES] = s[1023];
}

__global__ void k_fill(const int* __restrict__ ei) {
    int idx = blockIdx.x * blockDim.x + threadIdx.x;
    if (idx < N_EDGES) {
        int s = ei[idx];
        int d = ei[N_EDGES + idx];
        int p = atomicAdd(&g_pos[d], 1);
        g_col[p] = s;
        g_enorm[p] = g_dinv[s] * g_dinv[d];
    } else if (idx < EN) {
        int i = idx - N_EDGES;
        int p = atomicAdd(&g_pos[i], 1);
        g_col[p] = i;
        float di = g_dinv[i];
        g_enorm[p] = di * di;
    }
}

// ---------------- aggregation (fp16 gather) + fp32->bf16 hi/lo split --------
// One warp per node; lane owns D/32 contiguous dims (16B chunk at D=256,
// 8B at D=128) -> one load per edge per lane. Accumulate fp32.
template <int PE>
__device__ __forceinline__ void split_store(__nv_bfloat16* oh, __nv_bfloat16* ol,
                                            size_t off, const float* a) {
    union { __nv_bfloat162 b[PE / 2]; uint4 u4; uint2 u2; } H, L;
#pragma unroll
    for (int i = 0; i < PE / 2; i++) {
        __nv_bfloat16 h0 = __float2bfloat16(a[2 * i]);
        __nv_bfloat16 h1 = __float2bfloat16(a[2 * i + 1]);
        H.b[i] = __halves2bfloat162(h0, h1);
        L.b[i] = __halves2bfloat162(
            __float2bfloat16(a[2 * i]     - __bfloat162float(h0)),
            __float2bfloat16(a[2 * i + 1] - __bfloat162float(h1)));
    }
    if (PE == 8) {
        *reinterpret_cast<uint4*>(oh + off) = H.u4;
        *reinterpret_cast<uint4*>(ol + off) = L.u4;
    } else {
        *reinterpret_cast<uint2*>(oh + off) = H.u2;
        *reinterpret_cast<uint2*>(ol + off) = L.u2;
    }
}

template <int D>   // 128 or 256
__global__ __launch_bounds__(256) void k_agg_split(
        const __half* __restrict__ feat,
        __nv_bfloat16* __restrict__ oh,
        __nv_bfloat16* __restrict__ ol) {
    constexpr int PE = D / 32;               // dims per lane (4 or 8)
    const int warp = blockIdx.x * (blockDim.x >> 5) + (threadIdx.x >> 5);
    const int lane = threadIdx.x & 31;
    if (warp >= N_NODES) return;
    const int rs = g_row_ptr[warp];
    const int re = g_row_ptr[warp + 1];

    float accA[PE], accB[PE];
#pragma unroll
    for (int i = 0; i < PE; i++) { accA[i] = 0.f; accB[i] = 0.f; }

    auto fma_row = [&](int c, float w, float* acc) {
        if (PE == 8) {
            union { uint4 u; __half2 h[4]; } U;
            U.u = __ldg(reinterpret_cast<const uint4*>(feat) + (size_t)c * 32 + lane);
#pragma unroll
            for (int q = 0; q < 4; q++) {
                float2 f = __half22float2(U.h[q]);
                acc[2 * q]     = fmaf(w, f.x, acc[2 * q]);
                acc[2 * q + 1] = fmaf(w, f.y, acc[2 * q + 1]);
            }
        } else {
            union { uint2 u; __half2 h[2]; } U;
            U.u = __ldg(reinterpret_cast<const uint2*>(feat) + (size_t)c * 32 + lane);
#pragma unroll
            for (int q = 0; q < 2; q++) {
                float2 f = __half22float2(U.h[q]);
                acc[2 * q]     = fmaf(w, f.x, acc[2 * q]);
                acc[2 * q + 1] = fmaf(w, f.y, acc[2 * q + 1]);
            }
        }
    };

    for (int j = rs; j < re; j += 32) {
        int m = re - j; if (m > 32) m = 32;
        int c = 0; float w = 0.f;
        if (lane < m) { c = g_col[j + lane]; w = g_enorm[j + lane]; }
        int k = 0;
        for (; k + 1 < m; k += 2) {
            int   c0 = __shfl_sync(0xffffffffu, c, k);
            float w0 = __shfl_sync(0xffffffffu, w, k);
            int   c1 = __shfl_sync(0xffffffffu, c, k + 1);
            float w1 = __shfl_sync(0xffffffffu, w, k + 1);
            fma_row(c0, w0, accA);
            fma_row(c1, w1, accB);
        }
        if (k < m) {
            int   c0 = __shfl_sync(0xffffffffu, c, k);
            float w0 = __shfl_sync(0xffffffffu, w, k);
            fma_row(c0, w0, accA);
        }
    }
#pragma unroll
    for (int i = 0; i < PE; i++) accA[i] += accB[i];
    split_store<PE>(oh, ol, (size_t)warp * D + lane * PE, accA);
}

// ---------------- split-bf16 mma.sync GEMM (R6 config: 3-pass, occ 2) -------
// C = Ah@Bh^T + Ah@Bl^T + Al@Bh^T + bias, B stored [N=256, K] bf16.
// CTA 256 thr, tile 128x128x64, double-buffered cp.async (2 x 32 KB dynamic
// SMEM), SW128 swizzle, warps 4(M) x 2(N), warp tile 32x64 via m16n8k16.
// HALF_OUT: write __half activations (layers 1-2); else fp32 (layer 3).
#define STAGE_A 16384                     // 128 rows x 128 B
#define STAGE   32768                     // A + B per stage
#define SMEM_DYN (2 * STAGE)              // 65536

template <int KP, bool RELU, bool HALF_OUT>
__global__ __launch_bounds__(256, 2) void k_gemm_mma(
    const __nv_bfloat16* __restrict__ Ah, const __nv_bfloat16* __restrict__ Al,
    const __nv_bfloat16* __restrict__ Bh, const __nv_bfloat16* __restrict__ Bl,
    const float* __restrict__ bias, void* __restrict__ Cv) {
    extern __shared__ __align__(128) char smem[];
    const uint32_t sb = smem_to_u32(smem);
    const int tid  = threadIdx.x;
    const int wid  = tid >> 5;
    const int lane = tid & 31;
    const int wm   = wid >> 1;           // 0..3  (M)
    const int wn   = wid & 1;            // 0..1  (N)
    const int m0   = blockIdx.y * BM;
    const int n0   = blockIdx.x * BN;

    const __nv_bfloat16* Ap[3] = {Ah, Ah, Al};
    const __nv_bfloat16* Bp[3] = {Bh, Bl, Bh};
    constexpr int TP = KP / BK;          // tiles per part (2 or 4)
    constexpr int T  = 3 * TP;

    float acc[2][8][4];
#pragma unroll
    for (int i = 0; i < 2; i++)
#pragma unroll
        for (int j = 0; j < 8; j++)
#pragma unroll
            for (int q = 0; q < 4; q++) acc[i][j][q] = 0.f;

    auto load_tile = [&](int buf, int t) {
        const int part = t / TP;
        const int kc   = (t % TP) * BK;
        const __nv_bfloat16* Ag = Ap[part];
        const __nv_bfloat16* Bg = Bp[part];
        const uint32_t aB = sb + buf * STAGE;
        const uint32_t bB = aB + STAGE_A;
#pragma unroll
        for (int i = 0; i < 4; ++i) {
            int c   = tid + i * 256;           // 0..1023
            int row = c >> 3;
            int ch  = c & 7;
            uint32_t sw = (uint32_t)(ch ^ (row & 7)) << 4;
            cp_async16(aB + row * 128 + sw,
                       Ag + (size_t)(m0 + row) * KP + kc + ch * 8);
            cp_async16(bB + row * 128 + sw,
                       Bg + (size_t)(n0 + row) * KP + kc + ch * 8);
        }
    };

    load_tile(0, 0);
    cp_commit();

    for (int t = 0; t < T; ++t) {
        if (t + 1 < T) { load_tile((t + 1) & 1, t + 1); cp_commit(); cp_wait<1>(); }
        else           { cp_wait<0>(); }
        __syncthreads();

        const uint32_t aB = sb + (t & 1) * STAGE;
        const uint32_t bB = aB + STAGE_A;
#pragma unroll
        for (int ks = 0; ks < 4; ++ks) {
            uint32_t a[2][4];
#pragma unroll
            for (int mi = 0; mi < 2; ++mi) {
                int row = wm * 32 + mi * 16 + (lane & 15);
                uint32_t chunk = (uint32_t)((ks << 1) + (lane >> 4));
                uint32_t addr = aB + row * 128 + ((chunk ^ (row & 7)) << 4);
                ldsm_x4(a[mi], addr);
            }
            uint32_t b[8][2];
#pragma unroll
            for (int nj = 0; nj < 4; ++nj) {
                int g = lane >> 3;
                int nl = wn * 64 + nj * 16 + ((g >> 1) << 3) + (lane & 7);
                uint32_t chunk = (uint32_t)((ks << 1) + (g & 1));
                uint32_t addr = bB + nl * 128 + ((chunk ^ (nl & 7)) << 4);
                uint32_t r[4];
                ldsm_x4(r, addr);
                b[nj * 2 + 0][0] = r[0]; b[nj * 2 + 0][1] = r[1];
                b[nj * 2 + 1][0] = r[2]; b[nj * 2 + 1][1] = r[3];
            }
#pragma unroll
            for (int mi = 0; mi < 2; ++mi)
#pragma unroll
                for (int ni = 0; ni < 8; ++ni)
                    mma_bf16(acc[mi][ni], a[mi], b[ni]);
        }
        __syncthreads();
    }

    // epilogue: bias + relu, write fp16 (layers 1-2) or fp32 (layer 3)
    const int lr = lane >> 2;
    const int lc = (lane & 3) * 2;
#pragma unroll
    for (int mi = 0; mi < 2; ++mi) {
        int rb = m0 + wm * 32 + mi * 16 + lr;
#pragma unroll
        for (int half = 0; half < 2; ++half) {
            int r = rb + half * 8;
            if (r < N_NODES) {
#pragma unroll
                for (int ni = 0; ni < 8; ++ni) {
                    int col = n0 + wn * 64 + ni * 8 + lc;
                    float2 bv = *reinterpret_cast<const float2*>(bias + col);
                    float2 o;
                    o.x = acc[mi][ni][half * 2 + 0] + bv.x;
                    o.y = acc[mi][ni][half * 2 + 1] + bv.y;
                    if (RELU) { o.x = fmaxf(o.x, 0.f); o.y = fmaxf(o.y, 0.f); }
                    if (HALF_OUT) {
                        __half* crow = reinterpret_cast<__half*>(Cv) + (size_t)r * D_HID;
                        *reinterpret_cast<__half2*>(crow + col) = __floats2half2_rn(o.x, o.y);
                    } else {
                        float* crow = reinterpret_cast<float*>(Cv) + (size_t)r * D_HID;
                        *reinterpret_cast<float2*>(crow + col) = o;
                    }
                }
            }
        }
    }
}

// ---------------- launch ----------------------------------------------------
extern "C" void kernel_launch(void* const* d_in, const int* in_sizes, int n_in,
                              void* d_out, int out_size) {
    const float* x  = (const float*)d_in[0];
    const int*   ei = (const int*)  d_in[1];
    const float* W1 = (const float*)d_in[2];
    const float* b1 = (const float*)d_in[3];
    const float* W2 = (const float*)d_in[4];
    const float* b2 = (const float*)d_in[5];
    const float* W3 = (const float*)d_in[6];
    const float* b3 = (const float*)d_in[7];
    float* out = (float*)d_out;

    cudaFuncSetAttribute(k_gemm_mma<D_IN,  true,  true >, cudaFuncAttributeMaxDynamicSharedMemorySize, SMEM_DYN);
    cudaFuncSetAttribute(k_gemm_mma<D_HID, true,  true >, cudaFuncAttributeMaxDynamicSharedMemorySize, SMEM_DYN);
    cudaFuncSetAttribute(k_gemm_mma<D_HID, false, false>, cudaFuncAttributeMaxDynamicSharedMemorySize, SMEM_DYN);

    void *p_x16, *p_h16, *p_ah, *p_al, *p1h, *p1l, *p2h, *p2l, *p3h, *p3l;
    cudaGetSymbolAddress(&p_x16, g_x16);
    cudaGetSymbolAddress(&p_h16, g_h16);
    cudaGetSymbolAddress(&p_ah, g_ah);
    cudaGetSymbolAddress(&p_al, g_al);
    cudaGetSymbolAddress(&p1h, g_w1h); cudaGetSymbolAddress(&p1l, g_w1l);
    cudaGetSymbolAddress(&p2h, g_w2h); cudaGetSymbolAddress(&p2l, g_w2l);
    cudaGetSymbolAddress(&p3h, g_w3h); cudaGetSymbolAddress(&p3l, g_w3l);
    __half* x16 = (__half*)p_x16;
    __half* h16 = (__half*)p_h16;
    __nv_bfloat16* ah = (__nv_bfloat16*)p_ah;
    __nv_bfloat16* al = (__nv_bfloat16*)p_al;

    // 1) fused degree count + W split + x->fp16   2) scan   3) fill
    k_count_split<<<(L1_THREADS + 255) / 256, 256>>>(ei, W1, W2, W3, x);
    k_scan<<<1, 1024>>>();
    k_fill<<<(EN + 255) / 256, 256>>>(ei);

    const int aggBlocks = (N_NODES + 7) / 8;   // 8 warps/block, 1 warp/node
    dim3 gemmGrid(D_HID / BN, N_CTAS);

    // Layer 1: (A_hat x) W1 + b1, relu -> fp16 h
    k_agg_split<D_IN><<<aggBlocks, 256>>>(x16, ah, al);
    k_gemm_mma<D_IN, true, true><<<gemmGrid, 256, SMEM_DYN>>>(ah, al,
        (__nv_bfloat16*)p1h, (__nv_bfloat16*)p1l, b1, h16);

    // Layer 2 -> fp16 h
    k_agg_split<D_HID><<<aggBlocks, 256>>>(h16, ah, al);
    k_gemm_mma<D_HID, true, true><<<gemmGrid, 256, SMEM_DYN>>>(ah, al,
        (__nv_bfloat16*)p2h, (__nv_bfloat16*)p2l, b2, h16);

    // Layer 3 (no relu) -> fp32 output
    k_agg_split<D_HID><<<aggBlocks, 256>>>(h16, ah, al);
    k_gemm_mma<D_HID, false, false><<<gemmGrid, 256, SMEM_DYN>>>(ah, al,
        (__nv_bfloat16*)p3h, (__nv_bfloat16*)p3l, b3, out);
}

// round 9
// speedup vs baseline: 1.4034x; 1.4034x over previous
#include <cuda_runtime.h>
#include <cuda_bf16.h>
#include <cstdint>
#include <math.h>

#define N_NODES 50000
#define N_EDGES 500000
#define EN      (N_EDGES + N_NODES)   // 550000 incl. self loops
#define D_IN    128
#define D_HID   256
#define BM      128
#define BN      128
#define BK      64
#define N_CTAS  ((N_NODES + BM - 1) / BM)   // 391
#define M_PAD   (N_CTAS * BM)               // 50048

// ---------------- async-copy helpers (portable PTX, sm_80+) -----------------
__device__ __forceinline__ uint32_t smem_to_u32(const void* p) {
    uint32_t a;
    asm("{ .reg .u64 t; cvta.to.shared.u64 t, %1; cvt.u32.u64 %0, t; }" : "=r"(a) : "l"(p));
    return a;
}
__device__ __forceinline__ void cp_async16(uint32_t s, const void* g) {
    asm volatile("cp.async.cg.shared.global [%0], [%1], 16;" :: "r"(s), "l"(g));
}
__device__ __forceinline__ void cp_commit() {
    asm volatile("cp.async.commit_group;" ::: "memory");
}
template <int N>
__device__ __forceinline__ void cp_wait() {
    asm volatile("cp.async.wait_group %0;" :: "n"(N) : "memory");
}
__device__ __forceinline__ void ldsm_x4(uint32_t* r, uint32_t addr) {
    asm volatile("ldmatrix.sync.aligned.m8n8.x4.shared.b16 {%0,%1,%2,%3}, [%4];"
                 : "=r"(r[0]), "=r"(r[1]), "=r"(r[2]), "=r"(r[3]) : "r"(addr));
}
__device__ __forceinline__ void mma_bf16(float* c, const uint32_t* a, const uint32_t* b) {
    asm volatile(
        "mma.sync.aligned.m16n8k16.row.col.f32.bf16.bf16.f32 "
        "{%0,%1,%2,%3}, {%4,%5,%6,%7}, {%8,%9}, {%0,%1,%2,%3};"
        : "+f"(c[0]), "+f"(c[1]), "+f"(c[2]), "+f"(c[3])
        : "r"(a[0]), "r"(a[1]), "r"(a[2]), "r"(a[3]), "r"(b[0]), "r"(b[1]));
}

// ---------------- packed f32x2 helpers (sm_100-family PTX) ------------------
typedef unsigned long long u64;
__device__ __forceinline__ u64 pack_f32x2(float x, float y) {
    u64 r; asm("mov.b64 %0, {%1,%2};" : "=l"(r) : "f"(x), "f"(y)); return r;
}
__device__ __forceinline__ void unpack_f32x2(u64 v, float& x, float& y) {
    asm("mov.b64 {%0,%1}, %2;" : "=f"(x), "=f"(y) : "l"(v));
}
__device__ __forceinline__ void ffma2(u64& d, u64 a, u64 b) {
    asm("fma.rn.f32x2 %0, %1, %2, %0;" : "+l"(d) : "l"(a), "l"(b));
}
// 16B row load directly into two b64 (f32x2 operand) registers
__device__ __forceinline__ void ld_row64(const float* p, u64& a, u64& b) {
    asm volatile("ld.global.nc.v2.b64 {%0,%1}, [%2];" : "=l"(a), "=l"(b) : "l"(p));
}

// ---------------- device scratch (static globals; no allocation) ------------
__device__ int   g_deg[N_NODES];          // zeroed each replay by k_scan
__device__ int   g_row_ptr[N_NODES + 1];
__device__ int   g_pos[N_NODES];
__device__ __align__(8) int2 g_edge[EN];  // zipped {col, norm-bits}
__device__ float g_dinv[N_NODES];
__device__ __align__(16) float g_h[(size_t)N_NODES * D_HID];           // fp32 activations
__device__ __align__(16) __nv_bfloat16 g_ah[(size_t)M_PAD * D_HID];    // split-hi of agg
__device__ __align__(16) __nv_bfloat16 g_al[(size_t)M_PAD * D_HID];    // split-lo of agg
__device__ __align__(16) __nv_bfloat16 g_w1h[D_HID * D_IN];            // W^T [256,128]
__device__ __align__(16) __nv_bfloat16 g_w1l[D_HID * D_IN];
__device__ __align__(16) __nv_bfloat16 g_w2h[D_HID * D_HID];           // W^T [256,256]
__device__ __align__(16) __nv_bfloat16 g_w2l[D_HID * D_HID];
__device__ __align__(16) __nv_bfloat16 g_w3h[D_HID * D_HID];
__device__ __align__(16) __nv_bfloat16 g_w3l[D_HID * D_HID];

// ---------------- CSR + weight split (fused launch 1) ------------------------
#define W1_ELEMS (D_IN * D_HID)
#define W23_ELEMS (D_HID * D_HID)
#define SPLIT_ELEMS (W1_ELEMS + 2 * W23_ELEMS)   // 163840

__device__ __forceinline__ void split_one(const float* W, int K, int idx,
                                          __nv_bfloat16* oh, __nv_bfloat16* ol) {
    int k = idx / D_HID, n = idx % D_HID;
    float v = W[idx];
    __nv_bfloat16 h = __float2bfloat16(v);
    oh[(size_t)n * K + k] = h;
    ol[(size_t)n * K + k] = __float2bfloat16(v - __bfloat162float(h));
}

__global__ void k_count_split(const int* __restrict__ ei,
                              const float* __restrict__ W1,
                              const float* __restrict__ W2,
                              const float* __restrict__ W3) {
    int idx = blockIdx.x * blockDim.x + threadIdx.x;
    if (idx < N_EDGES) {
        atomicAdd(&g_deg[ei[N_EDGES + idx]], 1);
        return;
    }
    int j = idx - N_EDGES;
    if (j < W1_ELEMS) { split_one(W1, D_IN, j, g_w1h, g_w1l); return; }
    j -= W1_ELEMS;
    if (j < W23_ELEMS) { split_one(W2, D_HID, j, g_w2h, g_w2l); return; }
    j -= W23_ELEMS;
    if (j < W23_ELEMS) { split_one(W3, D_HID, j, g_w3h, g_w3l); }
}

// Single-block scan. Degree = g_deg[i] + 1 (self loop). Zeroes g_deg for the
// next graph replay (deterministic).
__global__ void k_scan() {
    __shared__ int s[1024];
    const int t = threadIdx.x;
    const int CH = (N_NODES + 1023) / 1024;
    int start = t * CH;
    int end = start + CH; if (end > N_NODES) end = N_NODES;
    if (start > N_NODES) start = N_NODES;
    int sum = 0;
#pragma unroll 4
    for (int i = start; i < end; i++) sum += g_deg[i] + 1;
    s[t] = sum;
    __syncthreads();
    for (int off = 1; off < 1024; off <<= 1) {
        int v = (t >= off) ? s[t - off] : 0;
        __syncthreads();
        s[t] += v;
        __syncthreads();
    }
    int prefix = (t == 0) ? 0 : s[t - 1];
    for (int i = start; i < end; i++) {
        int d = g_deg[i] + 1;
        g_deg[i] = 0;
        g_row_ptr[i] = prefix;
        g_pos[i] = prefix;
        g_dinv[i] = rsqrtf((float)d);
        prefix += d;
    }
    if (t == 0) g_row_ptr[N_NODES] = s[1023];
}

__global__ void k_fill(const int* __restrict__ ei) {
    int idx = blockIdx.x * blockDim.x + threadIdx.x;
    if (idx < N_EDGES) {
        int s = ei[idx];
        int d = ei[N_EDGES + idx];
        int p = atomicAdd(&g_pos[d], 1);
        g_edge[p] = make_int2(s, __float_as_int(g_dinv[s] * g_dinv[d]));
    } else if (idx < EN) {
        int i = idx - N_EDGES;
        int p = atomicAdd(&g_pos[i], 1);
        float di = g_dinv[i];
        g_edge[p] = make_int2(i, __float_as_int(di * di));
    }
}

// ---------------- aggregation + fp32->bf16 hi/lo split ----------------------
__device__ __forceinline__ void split_store4(__nv_bfloat16* oh, __nv_bfloat16* ol,
                                             size_t off, float4 a) {
    __nv_bfloat16 hx = __float2bfloat16(a.x);
    __nv_bfloat16 hy = __float2bfloat16(a.y);
    __nv_bfloat16 hz = __float2bfloat16(a.z);
    __nv_bfloat16 hw = __float2bfloat16(a.w);
    union { __nv_bfloat162 b[2]; uint2 u; } H, L;
    H.b[0] = __halves2bfloat162(hx, hy);
    H.b[1] = __halves2bfloat162(hz, hw);
    L.b[0] = __halves2bfloat162(__float2bfloat16(a.x - __bfloat162float(hx)),
                                __float2bfloat16(a.y - __bfloat162float(hy)));
    L.b[1] = __halves2bfloat162(__float2bfloat16(a.z - __bfloat162float(hz)),
                                __float2bfloat16(a.w - __bfloat162float(hw)));
    *reinterpret_cast<uint2*>(oh + off) = H.u;
    *reinterpret_cast<uint2*>(ol + off) = L.u;
}

// Warp per node. No shuffles: every lane reads the SAME g_edge[j] (L1
// broadcast), then its own 16B slice of the source row. Packed f32x2 FMAs.
// 2-way edge unroll with independent accumulator sets for MLP.
template <int D>   // 128 or 256
__global__ __launch_bounds__(256) void k_agg_split(
        const float* __restrict__ feat,
        __nv_bfloat16* __restrict__ oh,
        __nv_bfloat16* __restrict__ ol) {
    const int warp = blockIdx.x * (blockDim.x >> 5) + (threadIdx.x >> 5);
    const int lane = threadIdx.x & 31;
    if (warp >= N_NODES) return;
    const int rs = g_row_ptr[warp];
    const int re = g_row_ptr[warp + 1];

    u64 zero = pack_f32x2(0.f, 0.f);
    u64 aA0 = zero, aA1 = zero, aA2 = zero, aA3 = zero;
    u64 aB0 = zero, aB1 = zero, aB2 = zero, aB3 = zero;

    int j = rs;
    for (; j + 2 <= re; j += 2) {
        int2 e0 = __ldg(&g_edge[j]);
        int2 e1 = __ldg(&g_edge[j + 1]);
        u64 w0 = pack_f32x2(__int_as_float(e0.y), __int_as_float(e0.y));
        u64 w1 = pack_f32x2(__int_as_float(e1.y), __int_as_float(e1.y));
        const float* r0 = feat + (size_t)e0.x * D + lane * 4;
        const float* r1 = feat + (size_t)e1.x * D + lane * 4;
        u64 v0a, v0b, v1a, v1b;
        ld_row64(r0, v0a, v0b);
        ld_row64(r1, v1a, v1b);
        ffma2(aA0, w0, v0a); ffma2(aA1, w0, v0b);
        ffma2(aB0, w1, v1a); ffma2(aB1, w1, v1b);
        if (D == 256) {
            u64 u0a, u0b, u1a, u1b;
            ld_row64(r0 + 128, u0a, u0b);
            ld_row64(r1 + 128, u1a, u1b);
            ffma2(aA2, w0, u0a); ffma2(aA3, w0, u0b);
            ffma2(aB2, w1, u1a); ffma2(aB3, w1, u1b);
        }
    }
    if (j < re) {
        int2 e0 = __ldg(&g_edge[j]);
        u64 w0 = pack_f32x2(__int_as_float(e0.y), __int_as_float(e0.y));
        const float* r0 = feat + (size_t)e0.x * D + lane * 4;
        u64 v0a, v0b;
        ld_row64(r0, v0a, v0b);
        ffma2(aA0, w0, v0a); ffma2(aA1, w0, v0b);
        if (D == 256) {
            u64 u0a, u0b;
            ld_row64(r0 + 128, u0a, u0b);
            ffma2(aA2, w0, u0a); ffma2(aA3, w0, u0b);
        }
    }

    float4 o0;
    { float x0,y0,x1,y1,x2,y2,x3,y3;
      unpack_f32x2(aA0, x0, y0); unpack_f32x2(aB0, x1, y1);
      unpack_f32x2(aA1, x2, y2); unpack_f32x2(aB1, x3, y3);
      o0.x = x0 + x1; o0.y = y0 + y1; o0.z = x2 + x3; o0.w = y2 + y3; }
    split_store4(oh, ol, (size_t)warp * D + lane * 4, o0);
    if (D == 256) {
        float4 o1;
        float x0,y0,x1,y1,x2,y2,x3,y3;
        unpack_f32x2(aA2, x0, y0); unpack_f32x2(aB2, x1, y1);
        unpack_f32x2(aA3, x2, y2); unpack_f32x2(aB3, x3, y3);
        o1.x = x0 + x1; o1.y = y0 + y1; o1.z = x2 + x3; o1.w = y2 + y3;
        split_store4(oh, ol, (size_t)warp * D + 128 + lane * 4, o1);
    }
}

// ---------------- split-bf16 mma.sync GEMM (3-pass, 3-stage pipeline) -------
// C = Ah@Bh^T + Ah@Bl^T + Al@Bh^T + bias, B stored [N=256, K] bf16.
// CTA 256 thr, tile 128x128x64, 3-stage cp.async ring (3 x 32 KB dynamic
// SMEM, occ 2), SW128 swizzle, warps 4(M) x 2(N), warp tile 32x64.
// One __syncthreads per K-tile.
#define STAGE_A 16384                     // 128 rows x 128 B
#define STAGE   32768                     // A + B per stage
#define SMEM_DYN (3 * STAGE)              // 98304

template <int KP, bool RELU>
__global__ __launch_bounds__(256, 2) void k_gemm_mma(
    const __nv_bfloat16* __restrict__ Ah, const __nv_bfloat16* __restrict__ Al,
    const __nv_bfloat16* __restrict__ Bh, const __nv_bfloat16* __restrict__ Bl,
    const float* __restrict__ bias, float* __restrict__ C) {
    extern __shared__ __align__(128) char smem[];
    const uint32_t sb = smem_to_u32(smem);
    const int tid  = threadIdx.x;
    const int wid  = tid >> 5;
    const int lane = tid & 31;
    const int wm   = wid >> 1;           // 0..3  (M)
    const int wn   = wid & 1;            // 0..1  (N)
    const int m0   = blockIdx.y * BM;
    const int n0   = blockIdx.x * BN;

    const __nv_bfloat16* Ap[3] = {Ah, Ah, Al};
    const __nv_bfloat16* Bp[3] = {Bh, Bl, Bh};
    constexpr int TP = KP / BK;          // tiles per part (2 or 4)
    constexpr int T  = 3 * TP;

    float acc[2][8][4];
#pragma unroll
    for (int i = 0; i < 2; i++)
#pragma unroll
        for (int j = 0; j < 8; j++)
#pragma unroll
            for (int q = 0; q < 4; q++) acc[i][j][q] = 0.f;

    auto load_tile = [&](int buf, int t) {
        const int part = t / TP;
        const int kc   = (t % TP) * BK;
        const __nv_bfloat16* Ag = Ap[part];
        const __nv_bfloat16* Bg = Bp[part];
        const uint32_t aB = sb + buf * STAGE;
        const uint32_t bB = aB + STAGE_A;
#pragma unroll
        for (int i = 0; i < 4; ++i) {
            int c   = tid + i * 256;           // 0..1023
            int row = c >> 3;
            int ch  = c & 7;
            uint32_t sw = (uint32_t)(ch ^ (row & 7)) << 4;
            cp_async16(aB + row * 128 + sw,
                       Ag + (size_t)(m0 + row) * KP + kc + ch * 8);
            cp_async16(bB + row * 128 + sw,
                       Bg + (size_t)(n0 + row) * KP + kc + ch * 8);
        }
    };

    load_tile(0, 0); cp_commit();
    load_tile(1, 1); cp_commit();

    for (int t = 0; t < T; ++t) {
        if (t + 1 < T) cp_wait<1>(); else cp_wait<0>();
        __syncthreads();

        const uint32_t aB = sb + (t % 3) * STAGE;
        const uint32_t bB = aB + STAGE_A;
#pragma unroll
        for (int ks = 0; ks < 4; ++ks) {
            uint32_t a[2][4];
#pragma unroll
            for (int mi = 0; mi < 2; ++mi) {
                int row = wm * 32 + mi * 16 + (lane & 15);
                uint32_t chunk = (uint32_t)((ks << 1) + (lane >> 4));
                uint32_t addr = aB + row * 128 + ((chunk ^ (row & 7)) << 4);
                ldsm_x4(a[mi], addr);
            }
            uint32_t b[8][2];
#pragma unroll
            for (int nj = 0; nj < 4; ++nj) {
                int g = lane >> 3;
                int nl = wn * 64 + nj * 16 + ((g >> 1) << 3) + (lane & 7);
                uint32_t chunk = (uint32_t)((ks << 1) + (g & 1));
                uint32_t addr = bB + nl * 128 + ((chunk ^ (nl & 7)) << 4);
                uint32_t r[4];
                ldsm_x4(r, addr);
                b[nj * 2 + 0][0] = r[0]; b[nj * 2 + 0][1] = r[1];
                b[nj * 2 + 1][0] = r[2]; b[nj * 2 + 1][1] = r[3];
            }
#pragma unroll
            for (int mi = 0; mi < 2; ++mi)
#pragma unroll
                for (int ni = 0; ni < 8; ++ni)
                    mma_bf16(acc[mi][ni], a[mi], b[ni]);
        }

        if (t + 2 < T) { load_tile((t + 2) % 3, t + 2); cp_commit(); }
    }

    // epilogue: bias + relu, write fp32
    const int lr = lane >> 2;
    const int lc = (lane & 3) * 2;
#pragma unroll
    for (int mi = 0; mi < 2; ++mi) {
        int rb = m0 + wm * 32 + mi * 16 + lr;
#pragma unroll
        for (int half = 0; half < 2; ++half) {
            int r = rb + half * 8;
            if (r < N_NODES) {
                float* crow = C + (size_t)r * D_HID;
#pragma unroll
                for (int ni = 0; ni < 8; ++ni) {
                    int col = n0 + wn * 64 + ni * 8 + lc;
                    float2 bv = *reinterpret_cast<const float2*>(bias + col);
                    float2 o;
                    o.x = acc[mi][ni][half * 2 + 0] + bv.x;
                    o.y = acc[mi][ni][half * 2 + 1] + bv.y;
                    if (RELU) { o.x = fmaxf(o.x, 0.f); o.y = fmaxf(o.y, 0.f); }
                    *reinterpret_cast<float2*>(crow + col) = o;
                }
            }
        }
    }
}

// ---------------- launch ----------------------------------------------------
extern "C" void kernel_launch(void* const* d_in, const int* in_sizes, int n_in,
                              void* d_out, int out_size) {
    const float* x  = (const float*)d_in[0];
    const int*   ei = (const int*)  d_in[1];
    const float* W1 = (const float*)d_in[2];
    const float* b1 = (const float*)d_in[3];
    const float* W2 = (const float*)d_in[4];
    const float* b2 = (const float*)d_in[5];
    const float* W3 = (const float*)d_in[6];
    const float* b3 = (const float*)d_in[7];
    float* out = (float*)d_out;

    cudaFuncSetAttribute(k_gemm_mma<D_IN,  true >, cudaFuncAttributeMaxDynamicSharedMemorySize, SMEM_DYN);
    cudaFuncSetAttribute(k_gemm_mma<D_HID, true >, cudaFuncAttributeMaxDynamicSharedMemorySize, SMEM_DYN);
    cudaFuncSetAttribute(k_gemm_mma<D_HID, false>, cudaFuncAttributeMaxDynamicSharedMemorySize, SMEM_DYN);

    void *p_h, *p_ah, *p_al, *p1h, *p1l, *p2h, *p2l, *p3h, *p3l;
    cudaGetSymbolAddress(&p_h,  g_h);
    cudaGetSymbolAddress(&p_ah, g_ah);
    cudaGetSymbolAddress(&p_al, g_al);
    cudaGetSymbolAddress(&p1h, g_w1h); cudaGetSymbolAddress(&p1l, g_w1l);
    cudaGetSymbolAddress(&p2h, g_w2h); cudaGetSymbolAddress(&p2l, g_w2l);
    cudaGetSymbolAddress(&p3h, g_w3h); cudaGetSymbolAddress(&p3l, g_w3l);
    float* h = (float*)p_h;
    __nv_bfloat16* ah = (__nv_bfloat16*)p_ah;
    __nv_bfloat16* al = (__nv_bfloat16*)p_al;

    // 1) fused degree count + weight split   2) scan (+deg reset)   3) fill
    k_count_split<<<(N_EDGES + SPLIT_ELEMS + 255) / 256, 256>>>(ei, W1, W2, W3);
    k_scan<<<1, 1024>>>();
    k_fill<<<(EN + 255) / 256, 256>>>(ei);

    const int aggBlocks = (N_NODES + 7) / 8;   // 8 warps/block, 1 warp/node
    dim3 gemmGrid(D_HID / BN, N_CTAS);

    // Layer 1: (A_hat x) W1 + b1, relu       (agg1 = 4th launch -> ncu capture)
    k_agg_split<D_IN><<<aggBlocks, 256>>>(x, ah, al);
    k_gemm_mma<D_IN, true><<<gemmGrid, 256, SMEM_DYN>>>(ah, al,
        (__nv_bfloat16*)p1h, (__nv_bfloat16*)p1l, b1, h);

    // Layer 2
    k_agg_split<D_HID><<<aggBlocks, 256>>>(h, ah, al);
    k_gemm_mma<D_HID, true><<<gemmGrid, 256, SMEM_DYN>>>(ah, al,
        (__nv_bfloat16*)p2h, (__nv_bfloat16*)p2l, b2, h);

    // Layer 3 (no relu), straight to output
    k_agg_split<D_HID><<<aggBlocks, 256>>>(h, ah, al);
    k_gemm_mma<D_HID, false><<<gemmGrid, 256, SMEM_DYN>>>(ah, al,
        (__nv_bfloat16*)p3h, (__nv_bfloat16*)p3l, b3, out);
}